// round 11
// baseline (speedup 1.0000x reference)
#include <cuda_runtime.h>
#include <cuda_bf16.h>
#include <math.h>
#include <stdint.h>

// CustomLSTM: 2-layer LSTM, B=128, T=512, IN=64, H=1024, OUT=1
// Round 10: int8 fixed-point MMA (m16n8k32.s8) with SIGNED rounded two-plane
// split (zero-mean lo => dropped lo*lo term is unbiased noise, not bias).
// h scale 2^13, w scale 2^18. x projection stays bf16 3-term.

#define Bb    128
#define Tt    512
#define INP   64
#define Hh    1024
#define NBLK  128
#define NTHR  256

typedef unsigned int u32;
typedef unsigned short us;
typedef unsigned long long u64;
typedef signed char s8;

// ---- smem stage layout (bytes) ----
// int8 chunk view:  ActHi[128][80] @0, ActLo @10240, Whi[32][80] @20480, Wlo @23040
// bf16 x-chunk view: ActH us[128][72] @0, ActL @18432, WH @36864, WL @41472
#define STG_B    46080u
#define NSTG     3
#define SGATE_B  (NSTG * STG_B)            // 138240: float gate buffer [32][132]
#define HSTG_B   (SGATE_B + 16896u)        // 155136: h staging s8 [2][128][8]
#define DYN_SMEM (HSTG_B + 2048u + 256u)   // 157440 bytes

// ---------------- device scratch ----------------
__device__ __align__(128) s8 d_h0q[2][2][Bb][Hh];   // [buf][plane hi/lo][b][k]
__device__ __align__(128) s8 d_h1q[2][2][Bb][Hh];
__device__ __align__(128) us d_x[Tt][2][Bb][INP];   // x bf16 hi/lo planes
__device__ __align__(128) s8 d_w8[128u * 48u * 2u * 32u * 64u]; // [cta][chunk][pl][32][64]
__device__ __align__(128) us d_wx16[128u * 2u * 32u * 64u];     // Wx0 bf16 [cta][pl][32][64]
__device__ float d_bias0[4096], d_bias1[4096];
__device__ float d_bi0[Bb * Hh], d_bi1[Bb * Hh];
__device__ float d_h1f[Bb * Hh];
__device__ u32 g_count;
__device__ volatile u32 g_gen;
__device__ volatile u32 g_abort;

// ---------------- helpers ----------------
__device__ __forceinline__ u32 smem_u32(const void* p) {
    u32 a; asm("{ .reg .u64 t; cvta.to.shared.u64 t, %1; cvt.u32.u64 %0, t; }" : "=r"(a) : "l"(p));
    return a;
}
__device__ __forceinline__ void cpa16(u32 dst, const void* src) {
    asm volatile("cp.async.cg.shared.global [%0], [%1], 16;" :: "r"(dst), "l"(src));
}
#define CP_COMMIT() asm volatile("cp.async.commit_group;" ::: "memory")
#define CP_WAIT0()  asm volatile("cp.async.wait_group 0;" ::: "memory")
#define CP_WAIT1()  asm volatile("cp.async.wait_group 1;" ::: "memory")

__device__ __forceinline__ void ldsm4(u32* r, u32 addr) {
    asm volatile("ldmatrix.sync.aligned.m8n8.x4.shared.b16 {%0,%1,%2,%3}, [%4];"
                 : "=r"(r[0]), "=r"(r[1]), "=r"(r[2]), "=r"(r[3]) : "r"(addr));
}
__device__ __forceinline__ void mma_bf16(float* c, const u32* a, u32 b0, u32 b1) {
    asm volatile("mma.sync.aligned.m16n8k16.row.col.f32.bf16.bf16.f32 "
                 "{%0,%1,%2,%3}, {%4,%5,%6,%7}, {%8,%9}, {%0,%1,%2,%3};"
                 : "+f"(c[0]), "+f"(c[1]), "+f"(c[2]), "+f"(c[3])
                 : "r"(a[0]), "r"(a[1]), "r"(a[2]), "r"(a[3]), "r"(b0), "r"(b1));
}
__device__ __forceinline__ void mma_s8(int* c, const u32* a, u32 b0, u32 b1) {
    asm volatile("mma.sync.aligned.m16n8k32.row.col.s32.s8.s8.s32 "
                 "{%0,%1,%2,%3}, {%4,%5,%6,%7}, {%8,%9}, {%0,%1,%2,%3};"
                 : "+r"(c[0]), "+r"(c[1]), "+r"(c[2]), "+r"(c[3])
                 : "r"(a[0]), "r"(a[1]), "r"(a[2]), "r"(a[3]), "r"(b0), "r"(b1));
}

__device__ __forceinline__ float sigf(float x) { return __fdividef(1.f, 1.f + __expf(-x)); }
__device__ __forceinline__ float tanh_f(float x) {
    float xc = fminf(fmaxf(x, -15.f), 15.f);
    float e  = __expf(-2.f * xc);
    return (1.f - e) * __fdividef(1.f, 1.f + e);
}
__device__ __forceinline__ void bsplit(float v, us& hi, us& lo) {
    __nv_bfloat16 h = __float2bfloat16_rn(v);
    __nv_bfloat16 l = __float2bfloat16_rn(v - __bfloat162float(h));
    hi = __bfloat16_as_ushort(h); lo = __bfloat16_as_ushort(l);
}
// signed rounded split: q = hi*128 + lo, lo in [-64, 63]
__device__ __forceinline__ void qsplit(int q, s8& hi, s8& lo) {
    int h = (q + 64) >> 7;
    hi = (s8)h;
    lo = (s8)(q - (h << 7));
}

// ---------------- setup kernels ----------------
__global__ void setup_misc(const float* __restrict__ boundary,
                           const float* __restrict__ bx0, const float* __restrict__ bh0,
                           const float* __restrict__ bb0, const float* __restrict__ Wb0,
                           const float* __restrict__ bx1, const float* __restrict__ bh1,
                           const float* __restrict__ bb1, const float* __restrict__ Wb1)
{
    int idx = blockIdx.x * 256 + threadIdx.x;   // 131072
    if (idx == 0) { g_count = 0; g_gen = 0; g_abort = 0; }
    ((u32*)d_h0q)[idx] = 0u;                    // zero all h planes
    ((u32*)d_h1q)[idx] = 0u;
    int b = idx >> 10, j = idx & 1023;
    float p0 = boundary[b * 2 + 0], p1 = boundary[b * 2 + 1];
    d_bi0[idx] = p0 * Wb0[j * 2 + 0] + p1 * Wb0[j * 2 + 1] + bb0[j];
    d_bi1[idx] = p0 * Wb1[j * 2 + 0] + p1 * Wb1[j * 2 + 1] + bb1[j];
    if (idx < 4096) {
        d_bias0[idx] = bx0[idx] + bh0[idx];
        d_bias1[idx] = bx1[idx] + bh1[idx];
    }
}

__global__ void setup_x(const float* __restrict__ x)
{
    int idx = blockIdx.x * 256 + threadIdx.x;   // 4194304
    int k = idx & 63, b = (idx >> 6) & 127, t = idx >> 13;
    float v = x[b * (Tt * INP) + t * INP + k];
    us hi, lo; bsplit(v, hi, lo);
    d_x[t][0][b][k] = hi;
    d_x[t][1][b][k] = lo;
}

// int8 weight repack: chunk wc: 0-15 Uh0, 16-31 Wx1, 32-47 Uh1. scale 2^18.
__global__ void repack_w8(const float* __restrict__ Uh0, const float* __restrict__ Wx1,
                          const float* __restrict__ Uh1)
{
    int idx = blockIdx.x * 256 + threadIdx.x;   // 128*48*32*64 = 12582912
    int k   = idx & 63;
    int r   = (idx >> 6) & 31;
    int wc  = (idx >> 11) % 48;
    int cta = idx / (48 << 11);
    int grow = (r >> 3) * Hh + cta * 8 + (r & 7);
    float wv;
    if (wc < 16)      wv = Uh0[grow * Hh + wc * 64 + k];
    else if (wc < 32) wv = Wx1[grow * Hh + (wc - 16) * 64 + k];
    else              wv = Uh1[grow * Hh + (wc - 32) * 64 + k];
    int q = (int)rintf(wv * 262144.f);          // 2^18; |w|<=2^-5 -> |q|<=8192
    q = min(8192, max(-8192, q));
    s8 hi, lo; qsplit(q, hi, lo);
    u64 base = ((u64)(cta * 48 + wc)) * 2u * 2048u;
    d_w8[base + 0    + r * 64 + k] = hi;
    d_w8[base + 2048 + r * 64 + k] = lo;
}

__global__ void repack_wx(const float* __restrict__ Wx0)
{
    int idx = blockIdx.x * 256 + threadIdx.x;   // 262144
    int k   = idx & 63;
    int r   = (idx >> 6) & 31;
    int cta = idx >> 11;
    int grow = (r >> 3) * Hh + cta * 8 + (r & 7);
    float wv = Wx0[grow * INP + k];
    us hi, lo; bsplit(wv, hi, lo);
    d_wx16[((u32)cta * 2 + 0) * 2048 + r * 64 + k] = hi;
    d_wx16[((u32)cta * 2 + 1) * 2048 + r * 64 + k] = lo;
}

// ---------------- grid barrier (bounded, abort-safe) ----------------
__device__ __forceinline__ void grid_barrier(u32 target)
{
    __threadfence();
    __syncthreads();
    if (threadIdx.x == 0) {
        u32 old = atomicAdd(&g_count, 1u);
        if (old == NBLK - 1) {
            g_count = 0;
            __threadfence();
            g_gen = target;
        } else {
            u32 i = 0;
            while (g_gen < target) {
                __nanosleep(64);
                if (g_abort) break;
                if (++i > (1u << 24)) { g_abort = 1u; break; }
            }
        }
    }
    __syncthreads();
}

// ---------------- chunk staging ----------------
// layer0: ci==0 -> x bf16 chunk; ci 1..16 -> h0_prev int8 chunk ci-1 (Uh0)
// layer1: ci 0..15 -> h0_new int8 (Wx1); ci 16..31 -> h1_prev int8 (Uh1)
__device__ __forceinline__ void load_chunk(u32 Sa, int layer, int ci, int t, int cta, int tid)
{
    const int rd = t & 1, wr = rd ^ 1;
    if (layer == 0 && ci == 0) {
        const us* xb = &d_x[t][0][0][0];        // plane stride 8192 us
#pragma unroll
        for (int i = 0; i < 8; ++i) {           // act: 2048 x 16B
            int h = tid + i * 256;
            int pl = h >> 10, row = (h >> 3) & 127, seg = h & 7;
            cpa16(Sa + (u32)(pl * 18432 + row * 144 + seg * 16),
                  xb + pl * 8192 + row * 64 + seg * 8);
        }
        const us* wsrc = d_wx16 + (u32)cta * 2u * 2048u;
#pragma unroll
        for (int i = 0; i < 2; ++i) {           // w: 512 x 16B
            int h = tid + i * 256;
            int pl = h >> 8, row = (h >> 3) & 31, seg = h & 7;
            cpa16(Sa + (u32)(36864 + pl * 4608 + row * 144 + seg * 16),
                  wsrc + pl * 2048 + row * 64 + seg * 8);
        }
        return;
    }
    const s8* aBase; int k0; int widx;
    if (layer == 0)      { aBase = &d_h0q[rd][0][0][0]; k0 = (ci - 1) * 64; widx = ci - 1; }
    else if (ci < 16)    { aBase = &d_h0q[wr][0][0][0]; k0 = ci * 64;       widx = 16 + ci; }
    else                 { aBase = &d_h1q[rd][0][0][0]; k0 = (ci - 16) * 64; widx = 16 + ci; }

#pragma unroll
    for (int i = 0; i < 4; ++i) {               // act: 1024 x 16B (2 planes)
        int h = tid + i * 256;
        int pl = h >> 9, row = (h >> 2) & 127, seg = h & 3;
        cpa16(Sa + (u32)(pl * 10240 + row * 80 + seg * 16),
              aBase + pl * (Bb * Hh) + row * Hh + k0 + seg * 16);
    }
    const s8* wsrc = d_w8 + ((u64)(cta * 48 + widx)) * 2u * 2048u;
    {                                           // w: 256 x 16B
        int pl = tid >> 7, row = (tid >> 2) & 31, seg = tid & 3;
        cpa16(Sa + (u32)(20480 + pl * 2560 + row * 80 + seg * 16),
              wsrc + pl * 2048 + row * 64 + seg * 16);
    }
}

// ---------------- persistent LSTM kernel ----------------
__global__ void __launch_bounds__(NTHR, 1) lstm_mma()
{
    extern __shared__ __align__(16) uint8_t sm[];
    const int tid  = threadIdx.x;
    const int cta  = blockIdx.x;
    const int lane = tid & 31;
    const int wid  = tid >> 5;          // 0..7
    const int mrow = wid & 1;           // gate-row tile (0-15 / 16-31)
    const int wcol = wid >> 1;          // batch col group (x32)
    const u32 smA  = smem_u32(sm);

    float* sgate = (float*)(sm + SGATE_B);      // [32][132]
    s8*    hstg  = (s8*)(sm + HSTG_B);          // [2][128][8]

    // int8 frag byte offsets (80B rows)
    const u32 a8off  = (u32)((mrow * 16 + (lane & 15)) * 80 + (lane >> 4) * 16);
    const u32 b8off0 = (u32)((wcol * 32 + (lane & 15)) * 80 + (lane >> 4) * 16);
    const u32 b8off1 = b8off0 + 16 * 80;
    // bf16 frag byte offsets (144B rows)
    const u32 aoffB  = (u32)((mrow * 16 + (lane & 15)) * 144 + (lane >> 4) * 16);
    const u32 boffA  = (u32)((wcol * 32 + (lane & 7) + ((lane >> 4) & 1) * 8) * 144
                             + ((lane >> 3) & 1) * 16);
    const u32 boffBB = boffA + 16 * 144;

    const int j = cta * 8 + wid;
    float bg0[4], bg1[4], bif0[4], bif1[4];
#pragma unroll
    for (int g = 0; g < 4; ++g) {
        bg0[g] = d_bias0[g * Hh + j];
        bg1[g] = d_bias1[g * Hh + j];
    }
#pragma unroll
    for (int p = 0; p < 4; ++p) {
        bif0[p] = d_bi0[(lane + 32 * p) * Hh + j];
        bif1[p] = d_bi1[(lane + 32 * p) * Hh + j];
    }
    float c0[4] = {0.f, 0.f, 0.f, 0.f};
    float c1[4] = {0.f, 0.f, 0.f, 0.f};

    const float S1 = 7.62939453125e-6f;  // 2^-17  (hiW 2^-11 * hiA 2^-6)
    const float S2 = 5.9604645e-8f;      // 2^-24  (cross terms)

    for (int t = 0; t < Tt && !g_abort; ++t) {
        const int wr = (t & 1) ^ 1;
#pragma unroll 1
        for (int layer = 0; layer < 2; ++layer) {
            const int nc = layer ? 32 : 17;

            int   acc1[4][4], acc2[4][4];
            float accX[4][4];
#pragma unroll
            for (int nt = 0; nt < 4; ++nt)
#pragma unroll
                for (int q = 0; q < 4; ++q) {
                    acc1[nt][q] = 0; acc2[nt][q] = 0; accX[nt][q] = 0.f;
                }

            load_chunk(smA, layer, 0, t, cta, tid);
            CP_COMMIT();
            load_chunk(smA + STG_B, layer, 1, t, cta, tid);
            CP_COMMIT();

#pragma unroll 1
            for (int ci = 0; ci < nc; ++ci) {
                if (ci + 1 < nc) CP_WAIT1(); else CP_WAIT0();
                __syncthreads();

                if (ci + 2 < nc) {
                    load_chunk(smA + (u32)((ci + 2) % NSTG) * STG_B,
                               layer, ci + 2, t, cta, tid);
                    CP_COMMIT();
                }

                const u32 SaB = smA + (u32)(ci % NSTG) * STG_B;
                if (layer == 0 && ci == 0) {
                    // bf16 x chunk -> accX
#pragma unroll
                    for (int kk = 0; kk < 4; ++kk) {
                        const u32 k2 = (u32)kk * 32;
                        u32 wh[4], wl[4], bh1[4], bh2[4], bl1[4], bl2[4];
                        ldsm4(wh,  SaB + 36864 + aoffB + k2);
                        ldsm4(wl,  SaB + 41472 + aoffB + k2);
                        ldsm4(bh1, SaB + boffA  + k2);
                        ldsm4(bh2, SaB + boffBB + k2);
                        ldsm4(bl1, SaB + 18432 + boffA  + k2);
                        ldsm4(bl2, SaB + 18432 + boffBB + k2);
                        mma_bf16(accX[0], wh, bh1[0], bh1[1]);
                        mma_bf16(accX[1], wh, bh1[2], bh1[3]);
                        mma_bf16(accX[2], wh, bh2[0], bh2[1]);
                        mma_bf16(accX[3], wh, bh2[2], bh2[3]);
                        mma_bf16(accX[0], wl, bh1[0], bh1[1]);
                        mma_bf16(accX[1], wl, bh1[2], bh1[3]);
                        mma_bf16(accX[2], wl, bh2[0], bh2[1]);
                        mma_bf16(accX[3], wl, bh2[2], bh2[3]);
                        mma_bf16(accX[0], wh, bl1[0], bl1[1]);
                        mma_bf16(accX[1], wh, bl1[2], bl1[3]);
                        mma_bf16(accX[2], wh, bl2[0], bl2[1]);
                        mma_bf16(accX[3], wh, bl2[2], bl2[3]);
                    }
                } else {
                    // int8 chunk -> acc1/acc2
#pragma unroll
                    for (int kk = 0; kk < 64; kk += 32) {
                        u32 wh[4], wl[4], bh0[4], bh1[4], bl0[4], bl1[4];
                        ldsm4(wh,  SaB + 20480 + a8off + kk);
                        ldsm4(wl,  SaB + 23040 + a8off + kk);
                        ldsm4(bh0, SaB + b8off0 + kk);
                        ldsm4(bh1, SaB + b8off1 + kk);
                        ldsm4(bl0, SaB + 10240 + b8off0 + kk);
                        ldsm4(bl1, SaB + 10240 + b8off1 + kk);
                        // term1: hiW x hiA
                        mma_s8(acc1[0], wh, bh0[0], bh0[2]);
                        mma_s8(acc1[1], wh, bh0[1], bh0[3]);
                        mma_s8(acc1[2], wh, bh1[0], bh1[2]);
                        mma_s8(acc1[3], wh, bh1[1], bh1[3]);
                        // term2: hiW x loA + loW x hiA (same scale 2^-24)
                        mma_s8(acc2[0], wh, bl0[0], bl0[2]);
                        mma_s8(acc2[1], wh, bl0[1], bl0[3]);
                        mma_s8(acc2[2], wh, bl1[0], bl1[2]);
                        mma_s8(acc2[3], wh, bl1[1], bl1[3]);
                        mma_s8(acc2[0], wl, bh0[0], bh0[2]);
                        mma_s8(acc2[1], wl, bh0[1], bh0[3]);
                        mma_s8(acc2[2], wl, bh1[0], bh1[2]);
                        mma_s8(acc2[3], wl, bh1[1], bh1[3]);
                    }
                }
            }

            // ---- epilogue: accs -> sgate ----
            {
                const int row = mrow * 16 + (lane >> 2);
                const int col = wcol * 32 + (lane & 3) * 2;
#pragma unroll
                for (int nt = 0; nt < 4; ++nt) {
                    const int cb = col + nt * 8;
                    sgate[row * 132 + cb]           = (float)acc1[nt][0] * S1 + (float)acc2[nt][0] * S2 + accX[nt][0];
                    sgate[row * 132 + cb + 1]       = (float)acc1[nt][1] * S1 + (float)acc2[nt][1] * S2 + accX[nt][1];
                    sgate[(row + 8) * 132 + cb]     = (float)acc1[nt][2] * S1 + (float)acc2[nt][2] * S2 + accX[nt][2];
                    sgate[(row + 8) * 132 + cb + 1] = (float)acc1[nt][3] * S1 + (float)acc2[nt][3] * S2 + accX[nt][3];
                }
            }
            __syncthreads();

            // ---- cell: unit wid, batches lane+32p ----
            {
                const float* bg  = layer ? bg1 : bg0;
                const float* bif = layer ? bif1 : bif0;
                float* cc = layer ? c1 : c0;
#pragma unroll
                for (int p = 0; p < 4; ++p) {
                    const int b = lane + 32 * p;
                    float pi = sgate[(0  + wid) * 132 + b] + bg[0];
                    float pf = sgate[(8  + wid) * 132 + b] + bg[1] + bif[p];
                    float po = sgate[(16 + wid) * 132 + b] + bg[2];
                    float pg = sgate[(24 + wid) * 132 + b] + bg[3];
                    float iv = sigf(pi), fv = sigf(pf), ov = sigf(po), gg = tanh_f(pg);
                    float cn = fv * cc[p] + iv * gg;
                    cc[p] = cn;
                    float hv = ov * tanh_f(cn);
                    int q = (int)rintf(hv * 8192.f);     // 2^13, |q| <= 8192
                    q = min(8192, max(-8192, q));
                    s8 hi, lo; qsplit(q, hi, lo);
                    hstg[b * 8 + wid]        = hi;
                    hstg[1024 + b * 8 + wid] = lo;
                    if (layer == 1 && t == Tt - 1)
                        d_h1f[b * Hh + j] = hv;
                }
            }
            __syncthreads();

            // ---- coalesced h writeback: 8B per (plane, b) ----
            {
                const int pl = tid >> 7, b = tid & 127;
                uint2 v = *(const uint2*)(hstg + pl * 1024 + b * 8);
                s8* dst = (layer ? &d_h1q[wr][pl][b][cta * 8]
                                 : &d_h0q[wr][pl][b][cta * 8]);
                *(uint2*)dst = v;
            }

            if (layer == 0) {
                grid_barrier(t + 1);     // single barrier per step
                if (g_abort) break;
            } else {
                __syncthreads();         // protect hstg reuse within CTA
            }
        }
    }
}

// ---------------- fc head ----------------
__global__ void fc_kernel(const float* __restrict__ fcW,
                          const float* __restrict__ fcb,
                          float* __restrict__ out)
{
    __shared__ float red[256];
    int b = blockIdx.x, tid = threadIdx.x;
    float s = 0.f;
    for (int jj = tid; jj < Hh; jj += 256) s += d_h1f[b * Hh + jj] * fcW[jj];
    red[tid] = s;
    __syncthreads();
    for (int o = 128; o > 0; o >>= 1) {
        if (tid < o) red[tid] += red[tid + o];
        __syncthreads();
    }
    if (tid == 0) out[b] = red[0] + fcb[0];
}

// ---------------- launch (6 graph nodes) ----------------
extern "C" void kernel_launch(void* const* d_in, const int* in_sizes, int n_in,
                              void* d_out, int out_size)
{
    const float* x        = (const float*)d_in[0];
    const float* boundary = (const float*)d_in[1];
    const float* Wx0      = (const float*)d_in[2];
    const float* bx0      = (const float*)d_in[3];
    const float* Uh0      = (const float*)d_in[4];
    const float* bh0      = (const float*)d_in[5];
    const float* Wb0      = (const float*)d_in[6];
    const float* bb0      = (const float*)d_in[7];
    const float* Wx1      = (const float*)d_in[8];
    const float* bx1      = (const float*)d_in[9];
    const float* Uh1      = (const float*)d_in[10];
    const float* bh1      = (const float*)d_in[11];
    const float* Wb1      = (const float*)d_in[12];
    const float* bb1      = (const float*)d_in[13];
    const float* fcW      = (const float*)d_in[14];
    const float* fcb      = (const float*)d_in[15];
    float* out            = (float*)d_out;

    cudaFuncSetAttribute(lstm_mma, cudaFuncAttributeMaxDynamicSharedMemorySize, DYN_SMEM);

    setup_misc<<<(Bb * Hh) / 256, 256>>>(boundary, bx0, bh0, bb0, Wb0, bx1, bh1, bb1, Wb1);
    setup_x<<<(Tt * Bb * INP) / 256, 256>>>(x);
    repack_w8<<<(128 * 48 * 32 * 64) / 256, 256>>>(Uh0, Wx1, Uh1);
    repack_wx<<<(128 * 32 * 64) / 256, 256>>>(Wx0);
    lstm_mma<<<NBLK, NTHR, DYN_SMEM>>>();
    fc_kernel<<<Bb, 256>>>(fcW, fcb, out);
}

// round 12
// speedup vs baseline: 2.5838x; 2.5838x over previous
#include <cuda_runtime.h>
#include <cuda_fp16.h>
#include <math.h>
#include <stdint.h>

// CustomLSTM: 2-layer LSTM, B=128, T=512, IN=64, H=1024, OUT=1
// Round 12: R6 structure exactly, but fp16 HMMA with single-plane activations
// (h quant = fresh unbiased 2^-11 noise) and 2-plane fp16 weights (exact).
// x stays 2-plane (3-term) — one chunk per step. int8 IMMA path abandoned
// (measured ~4x slower per MAC on sm_103a).

#define Bb    128
#define Tt    512
#define INP   64
#define Hh    1024
#define NBLK  128
#define NTHR  256

typedef unsigned int u32;
typedef unsigned short us;
typedef unsigned long long u64;

// ---- smem layout (us = 2-byte units), identical footprint to R6 ----
#define ACT_PL   9216u              // 128*72 us (one act plane)
#define W_PL     2304u              // 32*72 us
#define STG_US   (2*ACT_PL + 2*W_PL)       // 23040 us / stage (ActL unused for h chunks)
#define NSTG     3
#define SGATE_US (NSTG * STG_US)           // float gate buffer [32][132]
#define HSTG_US  (SGATE_US + 8448u)        // h staging (1024 us used)
#define DYN_SMEM ((HSTG_US + 2048u) * 2u)  // bytes

// ---------------- device scratch ----------------
__device__ __align__(128) us d_h0[2][Bb][Hh];      // fp16 bits, single plane
__device__ __align__(128) us d_h1[2][Bb][Hh];
__device__ __align__(128) us d_x[Tt][2][Bb][INP];  // fp16 hi/lo planes
__device__ __align__(128) us d_w[128u * 49u * 2u * 32u * 64u]; // fp16 [cta][chunk][pl][32][64]
__device__ float d_bias0[4096], d_bias1[4096];
__device__ float d_bi0[Bb * Hh], d_bi1[Bb * Hh];
__device__ float d_h1f[Bb * Hh];
__device__ u32 g_count;
__device__ volatile u32 g_gen;
__device__ volatile u32 g_abort;

// ---------------- helpers ----------------
__device__ __forceinline__ u32 smem_u32(const void* p) {
    u32 a; asm("{ .reg .u64 t; cvta.to.shared.u64 t, %1; cvt.u32.u64 %0, t; }" : "=r"(a) : "l"(p));
    return a;
}
__device__ __forceinline__ void cpa16(u32 dst, const void* src) {
    asm volatile("cp.async.cg.shared.global [%0], [%1], 16;" :: "r"(dst), "l"(src));
}
#define CP_COMMIT() asm volatile("cp.async.commit_group;" ::: "memory")
#define CP_WAIT0()  asm volatile("cp.async.wait_group 0;" ::: "memory")
#define CP_WAIT1()  asm volatile("cp.async.wait_group 1;" ::: "memory")

__device__ __forceinline__ void ldsm4(u32* r, u32 addr) {
    asm volatile("ldmatrix.sync.aligned.m8n8.x4.shared.b16 {%0,%1,%2,%3}, [%4];"
                 : "=r"(r[0]), "=r"(r[1]), "=r"(r[2]), "=r"(r[3]) : "r"(addr));
}
__device__ __forceinline__ void mma_f16(float* c, const u32* a, u32 b0, u32 b1) {
    asm volatile("mma.sync.aligned.m16n8k16.row.col.f32.f16.f16.f32 "
                 "{%0,%1,%2,%3}, {%4,%5,%6,%7}, {%8,%9}, {%0,%1,%2,%3};"
                 : "+f"(c[0]), "+f"(c[1]), "+f"(c[2]), "+f"(c[3])
                 : "r"(a[0]), "r"(a[1]), "r"(a[2]), "r"(a[3]), "r"(b0), "r"(b1));
}

__device__ __forceinline__ float sigf(float x) { return __fdividef(1.f, 1.f + __expf(-x)); }
__device__ __forceinline__ float tanh_f(float x) {
    float xc = fminf(fmaxf(x, -15.f), 15.f);
    float e  = __expf(-2.f * xc);
    return (1.f - e) * __fdividef(1.f, 1.f + e);
}
// fp16 hi/lo split (residual capture; hi+lo exact to ~2^-21 rel)
__device__ __forceinline__ void hsplit(float v, us& hi, us& lo) {
    __half h = __float2half_rn(v);
    __half l = __float2half_rn(v - __half2float(h));
    hi = __half_as_ushort(h); lo = __half_as_ushort(l);
}

// ---------------- setup kernels ----------------
__global__ void setup_misc(const float* __restrict__ boundary,
                           const float* __restrict__ bx0, const float* __restrict__ bh0,
                           const float* __restrict__ bb0, const float* __restrict__ Wb0,
                           const float* __restrict__ bx1, const float* __restrict__ bh1,
                           const float* __restrict__ bb1, const float* __restrict__ Wb1)
{
    int idx = blockIdx.x * 256 + threadIdx.x;   // 131072
    if (idx == 0) { g_count = 0; g_gen = 0; g_abort = 0; }
    ((u32*)d_h0)[idx] = 0u;                     // zero both buffers (2*128*1024 us)
    ((u32*)d_h1)[idx] = 0u;
    int b = idx >> 10, j = idx & 1023;
    float p0 = boundary[b * 2 + 0], p1 = boundary[b * 2 + 1];
    d_bi0[idx] = p0 * Wb0[j * 2 + 0] + p1 * Wb0[j * 2 + 1] + bb0[j];
    d_bi1[idx] = p0 * Wb1[j * 2 + 0] + p1 * Wb1[j * 2 + 1] + bb1[j];
    if (idx < 4096) {
        d_bias0[idx] = bx0[idx] + bh0[idx];
        d_bias1[idx] = bx1[idx] + bh1[idx];
    }
}

__global__ void setup_x(const float* __restrict__ x)
{
    int idx = blockIdx.x * 256 + threadIdx.x;   // 4194304
    int k = idx & 63, b = (idx >> 6) & 127, t = idx >> 13;
    float v = x[b * (Tt * INP) + t * INP + k];
    us hi, lo; hsplit(v, hi, lo);
    d_x[t][0][b][k] = hi;
    d_x[t][1][b][k] = lo;
}

// chunk w: 0-15 Uh0 | 16 Wx0 | 17-32 Wx1 | 33-48 Uh1   (fp16 hi/lo planes)
__global__ void repack_w(const float* __restrict__ Uh0, const float* __restrict__ Wx0,
                         const float* __restrict__ Wx1, const float* __restrict__ Uh1)
{
    int idx = blockIdx.x * 256 + threadIdx.x;   // 12845056
    int k   = idx & 63;
    int r   = (idx >> 6) & 31;
    int w   = (idx >> 11) % 49;
    int cta = idx / (49 << 11);
    int g = r >> 3, u = r & 7;
    int grow = g * Hh + cta * 8 + u;
    float wv;
    if (w < 16)       wv = Uh0[grow * Hh + w * 64 + k];
    else if (w == 16) wv = Wx0[grow * INP + k];
    else if (w < 33)  wv = Wx1[grow * Hh + (w - 17) * 64 + k];
    else              wv = Uh1[grow * Hh + (w - 33) * 64 + k];
    us hi, lo; hsplit(wv, hi, lo);
    u64 base = ((u64)(cta * 49 + w)) * 2u * 2048u;
    d_w[base + 0    + r * 64 + k] = hi;
    d_w[base + 2048 + r * 64 + k] = lo;
}

// ---------------- grid barrier (bounded, abort-safe) ----------------
__device__ __forceinline__ void grid_barrier(u32 target)
{
    __threadfence();
    __syncthreads();
    if (threadIdx.x == 0) {
        u32 old = atomicAdd(&g_count, 1u);
        if (old == NBLK - 1) {
            g_count = 0;
            __threadfence();
            g_gen = target;
        } else {
            u32 i = 0;
            while (g_gen < target) {
                __nanosleep(64);
                if (g_abort) break;
                if (++i > (1u << 24)) { g_abort = 1u; break; }
            }
        }
    }
    __syncthreads();
}

// ---------------- chunk staging ----------------
// w: 0..15 h0_prev | 16 x_t (2 planes) | 17..32 h0_new | 33..48 h1_prev
__device__ __forceinline__ void load_chunk(u32 Sa, int w, int t, int cta, int tid)
{
    int rd = t & 1, wr = rd ^ 1;
    if (w == 16) {
        const us* xb = &d_x[t][0][0][0];        // plane stride 8192 us
#pragma unroll
        for (int i = 0; i < 4; ++i) {           // ActH (x hi): 512 x 16B
            int idx = tid + i * 256;
            int row = idx >> 3, seg = idx & 7;
            cpa16(Sa + (row * 72 + seg * 8) * 2, xb + row * INP + seg * 8);
        }
#pragma unroll
        for (int i = 0; i < 4; ++i) {           // ActL (x lo)
            int idx = tid + i * 256;
            int row = idx >> 3, seg = idx & 7;
            cpa16(Sa + (ACT_PL + row * 72 + seg * 8) * 2, xb + 8192 + row * INP + seg * 8);
        }
    } else {
        const us* aH;
        if (w < 16)      aH = &d_h0[rd][0][w * 64];
        else if (w < 33) aH = &d_h0[wr][0][(w - 17) * 64];
        else             aH = &d_h1[rd][0][(w - 33) * 64];
#pragma unroll
        for (int i = 0; i < 4; ++i) {           // ActH only (single plane)
            int idx = tid + i * 256;
            int row = idx >> 3, seg = idx & 7;
            cpa16(Sa + (row * 72 + seg * 8) * 2, aH + row * Hh + seg * 8);
        }
    }
    const us* wsrc = d_w + ((u64)(cta * 49 + w)) * 2u * 2048u;
#pragma unroll
    for (int i = 0; i < 2; ++i) {               // W hi+lo: 512 x 16B
        int idx = tid + i * 256;
        int pl = idx >> 8, row = (idx >> 3) & 31, seg = idx & 7;
        cpa16(Sa + (2 * ACT_PL + pl * W_PL + row * 72 + seg * 8) * 2,
              wsrc + pl * 2048 + row * 64 + seg * 8);
    }
}

// ---------------- persistent LSTM kernel ----------------
__global__ void __launch_bounds__(NTHR, 1) lstm_mma()
{
    extern __shared__ __align__(16) us sm[];
    const int tid  = threadIdx.x;
    const int cta  = blockIdx.x;
    const int lane = tid & 31;
    const int wid  = tid >> 5;
    const int mrow = wid & 1;
    const int wcol = wid >> 1;
    const u32 smA  = smem_u32(sm);

    float* sgate = (float*)(sm + SGATE_US);
    us*    hstg  = sm + HSTG_US;                // [128][8] fp16

    // ldmatrix per-lane source offsets (us units within a stage) — same as R6
    const u32 aoff  = (u32)((mrow * 16 + (lane & 15)) * 72 + ((lane >> 4) * 8));
    const u32 boffA = (u32)((wcol * 32 + (lane & 7) + ((lane >> 4) & 1) * 8) * 72
                            + (((lane >> 3) & 1) * 8));
    const u32 boffB = boffA + 16 * 72;

    const int j = cta * 8 + wid;
    float bg0[4], bg1[4], bif0[4], bif1[4];
#pragma unroll
    for (int g = 0; g < 4; ++g) {
        bg0[g] = d_bias0[g * Hh + j];
        bg1[g] = d_bias1[g * Hh + j];
    }
#pragma unroll
    for (int p = 0; p < 4; ++p) {
        bif0[p] = d_bi0[(lane + 32 * p) * Hh + j];
        bif1[p] = d_bi1[(lane + 32 * p) * Hh + j];
    }
    float c0[4] = {0.f, 0.f, 0.f, 0.f};
    float c1[4] = {0.f, 0.f, 0.f, 0.f};

    for (int t = 0; t < Tt && !g_abort; ++t) {
        const int wr = (t & 1) ^ 1;
#pragma unroll 1
        for (int layer = 0; layer < 2; ++layer) {
            const int wbeg = layer ? 17 : 0;
            const int nc   = layer ? 32 : 17;

            float acc[4][4];
#pragma unroll
            for (int nt = 0; nt < 4; ++nt)
#pragma unroll
                for (int q = 0; q < 4; ++q) acc[nt][q] = 0.f;

            // prologue: 2 chunks in flight
            load_chunk(smA, wbeg, t, cta, tid);
            CP_COMMIT();
            load_chunk(smA + STG_US * 2, wbeg + 1, t, cta, tid);
            CP_COMMIT();

#pragma unroll 1
            for (int ci = 0; ci < nc; ++ci) {
                if (ci + 1 < nc) CP_WAIT1(); else CP_WAIT0();
                __syncthreads();

                const bool isx = (layer == 0) && (ci == 16);
                const u32 SaB  = smA + (u32)(ci % NSTG) * (STG_US * 2);
                const u32 actH = SaB;
                const u32 actL = SaB + ACT_PL * 2;
                const u32 whB  = SaB + (2 * ACT_PL) * 2;
                const u32 wlB  = SaB + (2 * ACT_PL + W_PL) * 2;
#pragma unroll
                for (int kk = 0; kk < 64; kk += 16) {
                    const u32 k2 = (u32)kk * 2;
                    u32 wh[4], wl[4], b1[4], b2[4];
                    ldsm4(wh, whB  + aoff * 2 + k2);
                    ldsm4(wl, wlB  + aoff * 2 + k2);
                    ldsm4(b1, actH + boffA * 2 + k2);
                    ldsm4(b2, actH + boffB * 2 + k2);

                    mma_f16(acc[0], wh, b1[0], b1[1]);
                    mma_f16(acc[1], wh, b1[2], b1[3]);
                    mma_f16(acc[2], wh, b2[0], b2[1]);
                    mma_f16(acc[3], wh, b2[2], b2[3]);
                    mma_f16(acc[0], wl, b1[0], b1[1]);
                    mma_f16(acc[1], wl, b1[2], b1[3]);
                    mma_f16(acc[2], wl, b2[0], b2[1]);
                    mma_f16(acc[3], wl, b2[2], b2[3]);

                    if (isx) {                  // x chunk: + wh x act_lo
                        u32 l1[4], l2[4];
                        ldsm4(l1, actL + boffA * 2 + k2);
                        ldsm4(l2, actL + boffB * 2 + k2);
                        mma_f16(acc[0], wh, l1[0], l1[1]);
                        mma_f16(acc[1], wh, l1[2], l1[3]);
                        mma_f16(acc[2], wh, l2[0], l2[1]);
                        mma_f16(acc[3], wh, l2[2], l2[3]);
                    }
                }

                if (ci + 2 < nc) {
                    load_chunk(smA + (u32)((ci + 2) % NSTG) * (STG_US * 2),
                               wbeg + ci + 2, t, cta, tid);
                    CP_COMMIT();
                }
            }

            // ---- epilogue: acc -> sgate ----
            {
                const int row = mrow * 16 + (lane >> 2);
                const int col = wcol * 32 + (lane & 3) * 2;
#pragma unroll
                for (int nt = 0; nt < 4; ++nt) {
                    const int cb = col + nt * 8;
                    sgate[row * 132 + cb]           = acc[nt][0];
                    sgate[row * 132 + cb + 1]       = acc[nt][1];
                    sgate[(row + 8) * 132 + cb]     = acc[nt][2];
                    sgate[(row + 8) * 132 + cb + 1] = acc[nt][3];
                }
            }
            __syncthreads();

            // ---- cell: unit wid, batches lane+32p ----
            {
                const float* bg  = layer ? bg1 : bg0;
                const float* bif = layer ? bif1 : bif0;
                float* cc = layer ? c1 : c0;
#pragma unroll
                for (int p = 0; p < 4; ++p) {
                    const int b = lane + 32 * p;
                    float pi = sgate[(0  + wid) * 132 + b] + bg[0];
                    float pf = sgate[(8  + wid) * 132 + b] + bg[1] + bif[p];
                    float po = sgate[(16 + wid) * 132 + b] + bg[2];
                    float pg = sgate[(24 + wid) * 132 + b] + bg[3];
                    float iv = sigf(pi), fv = sigf(pf), ov = sigf(po), gg = tanh_f(pg);
                    float cn = fv * cc[p] + iv * gg;
                    cc[p] = cn;
                    float hv = ov * tanh_f(cn);
                    hstg[b * 8 + wid] = __half_as_ushort(__float2half_rn(hv));
                    if (layer == 1 && t == Tt - 1)
                        d_h1f[b * Hh + j] = hv;
                }
            }
            __syncthreads();

            // ---- coalesced h writeback: 16B per batch row ----
            if (tid < 128) {
                const int b = tid;
                uint4 v = *(const uint4*)(hstg + b * 8);
                us* dst = (layer ? &d_h1[wr][b][cta * 8]
                                 : &d_h0[wr][b][cta * 8]);
                *(uint4*)dst = v;
            }

            if (layer == 0) {
                grid_barrier(t + 1);     // single barrier per step
                if (g_abort) break;
            } else {
                __syncthreads();         // protect hstg reuse within CTA
            }
        }
    }
}

// ---------------- fc head ----------------
__global__ void fc_kernel(const float* __restrict__ fcW,
                          const float* __restrict__ fcb,
                          float* __restrict__ out)
{
    __shared__ float red[256];
    int b = blockIdx.x, tid = threadIdx.x;
    float s = 0.f;
    for (int jj = tid; jj < Hh; jj += 256) s += d_h1f[b * Hh + jj] * fcW[jj];
    red[tid] = s;
    __syncthreads();
    for (int o = 128; o > 0; o >>= 1) {
        if (tid < o) red[tid] += red[tid + o];
        __syncthreads();
    }
    if (tid == 0) out[b] = red[0] + fcb[0];
}

// ---------------- launch (5 graph nodes) ----------------
extern "C" void kernel_launch(void* const* d_in, const int* in_sizes, int n_in,
                              void* d_out, int out_size)
{
    const float* x        = (const float*)d_in[0];
    const float* boundary = (const float*)d_in[1];
    const float* Wx0      = (const float*)d_in[2];
    const float* bx0      = (const float*)d_in[3];
    const float* Uh0      = (const float*)d_in[4];
    const float* bh0      = (const float*)d_in[5];
    const float* Wb0      = (const float*)d_in[6];
    const float* bb0      = (const float*)d_in[7];
    const float* Wx1      = (const float*)d_in[8];
    const float* bx1      = (const float*)d_in[9];
    const float* Uh1      = (const float*)d_in[10];
    const float* bh1      = (const float*)d_in[11];
    const float* Wb1      = (const float*)d_in[12];
    const float* bb1      = (const float*)d_in[13];
    const float* fcW      = (const float*)d_in[14];
    const float* fcb      = (const float*)d_in[15];
    float* out            = (float*)d_out;

    cudaFuncSetAttribute(lstm_mma, cudaFuncAttributeMaxDynamicSharedMemorySize, DYN_SMEM);

    setup_misc<<<(Bb * Hh) / 256, 256>>>(boundary, bx0, bh0, bb0, Wb0, bx1, bh1, bb1, Wb1);
    setup_x<<<(Tt * Bb * INP) / 256, 256>>>(x);
    repack_w<<<(128 * 49 * 32 * 64) / 256, 256>>>(Uh0, Wx0, Wx1, Uh1);
    lstm_mma<<<NBLK, NTHR, DYN_SMEM>>>();
    fc_kernel<<<Bb, 256>>>(fcW, fcb, out);
}

// round 13
// speedup vs baseline: 2.9218x; 1.1308x over previous
#include <cuda_runtime.h>
#include <cuda_fp16.h>
#include <math.h>
#include <stdint.h>

// CustomLSTM: 2-layer LSTM, B=128, T=512, IN=64, H=1024, OUT=1
// Round 13: fp16 HMMA (single-plane act, 2-plane weights), K=128 chunks
// (25 chunks/step vs 49), in-register fragment double-buffering, and the x
// projection folded into one uniform chunk (x_hi|x_lo cols, Wx0_hi duplicated).

#define Bb    128
#define Tt    512
#define INP   64
#define Hh    1024
#define NBLK  128
#define NTHR  256

typedef unsigned int u32;
typedef unsigned short us;
typedef unsigned long long u64;

// ---- smem layout (bytes) ----
// stage: Act[128 rows][272B] @0, Whi[32][272B] @34816, Wlo @43520
#define STG_B    52224u
#define NSTG     3
#define SGATE_B  (NSTG * STG_B)            // 156672: float gate buffer [32][132]
#define HSTG_B   (SGATE_B + 16896u)        // 173568: h staging fp16 [128][8]
#define DYN_SMEM (HSTG_B + 2048u + 256u)   // 175872 bytes

// ---------------- device scratch ----------------
__device__ __align__(128) us d_h0[2][Bb][Hh];      // fp16 bits, single plane
__device__ __align__(128) us d_h1[2][Bb][Hh];
__device__ __align__(128) us d_x[Tt][2][Bb][INP];  // fp16 hi/lo planes
__device__ __align__(128) us d_w[128u * 25u * 2u * 32u * 128u]; // [cta][chunk][pl][32][128]
__device__ float d_bias0[4096], d_bias1[4096];
__device__ float d_bi0[Bb * Hh], d_bi1[Bb * Hh];
__device__ float d_h1f[Bb * Hh];
__device__ u32 g_count;
__device__ volatile u32 g_gen;
__device__ volatile u32 g_abort;

// ---------------- helpers ----------------
__device__ __forceinline__ u32 smem_u32(const void* p) {
    u32 a; asm("{ .reg .u64 t; cvta.to.shared.u64 t, %1; cvt.u32.u64 %0, t; }" : "=r"(a) : "l"(p));
    return a;
}
__device__ __forceinline__ void cpa16(u32 dst, const void* src) {
    asm volatile("cp.async.cg.shared.global [%0], [%1], 16;" :: "r"(dst), "l"(src));
}
#define CP_COMMIT() asm volatile("cp.async.commit_group;" ::: "memory")
#define CP_WAIT0()  asm volatile("cp.async.wait_group 0;" ::: "memory")
#define CP_WAIT1()  asm volatile("cp.async.wait_group 1;" ::: "memory")

__device__ __forceinline__ void ldsm4(u32* r, u32 addr) {
    asm volatile("ldmatrix.sync.aligned.m8n8.x4.shared.b16 {%0,%1,%2,%3}, [%4];"
                 : "=r"(r[0]), "=r"(r[1]), "=r"(r[2]), "=r"(r[3]) : "r"(addr));
}
__device__ __forceinline__ void mma_f16(float* c, const u32* a, u32 b0, u32 b1) {
    asm volatile("mma.sync.aligned.m16n8k16.row.col.f32.f16.f16.f32 "
                 "{%0,%1,%2,%3}, {%4,%5,%6,%7}, {%8,%9}, {%0,%1,%2,%3};"
                 : "+f"(c[0]), "+f"(c[1]), "+f"(c[2]), "+f"(c[3])
                 : "r"(a[0]), "r"(a[1]), "r"(a[2]), "r"(a[3]), "r"(b0), "r"(b1));
}

__device__ __forceinline__ float sigf(float x) { return __fdividef(1.f, 1.f + __expf(-x)); }
__device__ __forceinline__ float tanh_f(float x) {
    float xc = fminf(fmaxf(x, -15.f), 15.f);
    float e  = __expf(-2.f * xc);
    return (1.f - e) * __fdividef(1.f, 1.f + e);
}
__device__ __forceinline__ void hsplit(float v, us& hi, us& lo) {
    __half h = __float2half_rn(v);
    __half l = __float2half_rn(v - __half2float(h));
    hi = __half_as_ushort(h); lo = __half_as_ushort(l);
}

// ---------------- setup kernels ----------------
__global__ void setup_misc(const float* __restrict__ boundary,
                           const float* __restrict__ bx0, const float* __restrict__ bh0,
                           const float* __restrict__ bb0, const float* __restrict__ Wb0,
                           const float* __restrict__ bx1, const float* __restrict__ bh1,
                           const float* __restrict__ bb1, const float* __restrict__ Wb1)
{
    int idx = blockIdx.x * 256 + threadIdx.x;   // 131072
    if (idx == 0) { g_count = 0; g_gen = 0; g_abort = 0; }
    ((u32*)d_h0)[idx] = 0u;
    ((u32*)d_h1)[idx] = 0u;
    int b = idx >> 10, j = idx & 1023;
    float p0 = boundary[b * 2 + 0], p1 = boundary[b * 2 + 1];
    d_bi0[idx] = p0 * Wb0[j * 2 + 0] + p1 * Wb0[j * 2 + 1] + bb0[j];
    d_bi1[idx] = p0 * Wb1[j * 2 + 0] + p1 * Wb1[j * 2 + 1] + bb1[j];
    if (idx < 4096) {
        d_bias0[idx] = bx0[idx] + bh0[idx];
        d_bias1[idx] = bx1[idx] + bh1[idx];
    }
}

__global__ void setup_x(const float* __restrict__ x)
{
    int idx = blockIdx.x * 256 + threadIdx.x;   // 4194304
    int k = idx & 63, b = (idx >> 6) & 127, t = idx >> 13;
    float v = x[b * (Tt * INP) + t * INP + k];
    us hi, lo; hsplit(v, hi, lo);
    d_x[t][0][b][k] = hi;
    d_x[t][1][b][k] = lo;
}

// chunk wc: 0-7 Uh0 (K128) | 8 x-special (Wx0_hi dup / Wx0_lo|0) |
//           9-16 Wx1 (K128) | 17-24 Uh1 (K128)
__global__ void repack_w(const float* __restrict__ Uh0, const float* __restrict__ Wx0,
                         const float* __restrict__ Wx1, const float* __restrict__ Uh1)
{
    int idx = blockIdx.x * 256 + threadIdx.x;   // 128*25*32*128 = 13107200
    int k   = idx & 127;
    int r   = (idx >> 7) & 31;
    int wc  = (idx >> 12) % 25;
    int cta = idx / (25 << 12);
    int grow = (r >> 3) * Hh + cta * 8 + (r & 7);
    us hi, lo;
    if (wc == 8) {
        // x chunk: cols 0-63 pair with x_hi, cols 64-127 pair with x_lo
        float wv = Wx0[grow * INP + (k & 63)];
        hsplit(wv, hi, lo);
        if (k >= 64) lo = 0;                   // drop Wx0_lo * x_lo (negligible)
    } else {
        float wv;
        if (wc < 8)       wv = Uh0[grow * Hh + wc * 128 + k];
        else if (wc < 17) wv = Wx1[grow * Hh + (wc - 9) * 128 + k];
        else              wv = Uh1[grow * Hh + (wc - 17) * 128 + k];
        hsplit(wv, hi, lo);
    }
    u64 base = ((u64)(cta * 25 + wc)) * 2u * 4096u;
    d_w[base + 0    + r * 128 + k] = hi;
    d_w[base + 4096 + r * 128 + k] = lo;
}

// ---------------- grid barrier (bounded, abort-safe) ----------------
__device__ __forceinline__ void grid_barrier(u32 target)
{
    __threadfence();
    __syncthreads();
    if (threadIdx.x == 0) {
        u32 old = atomicAdd(&g_count, 1u);
        if (old == NBLK - 1) {
            g_count = 0;
            __threadfence();
            g_gen = target;
        } else {
            u32 i = 0;
            while (g_gen < target) {
                __nanosleep(64);
                if (g_abort) break;
                if (++i > (1u << 24)) { g_abort = 1u; break; }
            }
        }
    }
    __syncthreads();
}

// ---------------- chunk staging ----------------
// layer0: ci 0..7 h0_prev slices, ci 8 = x special
// layer1: ci 0..7 h0_new slices, ci 8..15 h1_prev slices
__device__ __forceinline__ void load_chunk(u32 Sa, int layer, int ci, int t, int cta, int tid)
{
    const int rd = t & 1, wr = rd ^ 1;
    const int wc = layer ? (9 + ci) : ci;

    if (layer == 0 && ci == 8) {
        const us* xb = &d_x[t][0][0][0];        // plane stride 8192 us
#pragma unroll
        for (int i = 0; i < 8; ++i) {           // act: 2048 x 16B
            int idx = tid + i * 256;
            int row = idx >> 4, seg = idx & 15;
            const us* src = (seg < 8) ? (xb + row * INP + seg * 8)
                                      : (xb + 8192 + row * INP + (seg - 8) * 8);
            cpa16(Sa + (u32)(row * 272 + seg * 16), src);
        }
    } else {
        const us* aH; int k0;
        if (layer == 0)   { aH = &d_h0[rd][0][0]; k0 = ci * 128; }
        else if (ci < 8)  { aH = &d_h0[wr][0][0]; k0 = ci * 128; }
        else              { aH = &d_h1[rd][0][0]; k0 = (ci - 8) * 128; }
#pragma unroll
        for (int i = 0; i < 8; ++i) {           // act: 2048 x 16B
            int idx = tid + i * 256;
            int row = idx >> 4, seg = idx & 15;
            cpa16(Sa + (u32)(row * 272 + seg * 16), aH + row * Hh + k0 + seg * 8);
        }
    }
    const us* wsrc = d_w + ((u64)(cta * 25 + wc)) * 2u * 4096u;
#pragma unroll
    for (int i = 0; i < 4; ++i) {               // W hi+lo: 1024 x 16B
        int idx = tid + i * 256;
        int pl = idx >> 9, row = (idx >> 4) & 31, seg = idx & 15;
        cpa16(Sa + (u32)(34816 + pl * 8704 + row * 272 + seg * 16),
              wsrc + pl * 4096 + row * 128 + seg * 8);
    }
}

// ---------------- persistent LSTM kernel ----------------
__global__ void __launch_bounds__(NTHR, 1) lstm_mma()
{
    extern __shared__ __align__(16) uint8_t sm[];
    const int tid  = threadIdx.x;
    const int cta  = blockIdx.x;
    const int lane = tid & 31;
    const int wid  = tid >> 5;
    const int mrow = wid & 1;
    const int wcol = wid >> 1;
    const u32 smA  = smem_u32(sm);

    float* sgate = (float*)(sm + SGATE_B);
    us*    hstg  = (us*)(sm + HSTG_B);          // [128][8] fp16

    // ldmatrix per-lane source byte offsets within a stage (272B act/W rows)
    const u32 aoffW = (u32)((mrow * 16 + (lane & 15)) * 272 + (lane >> 4) * 16);
    const u32 boffA = (u32)((wcol * 32 + (lane & 7) + ((lane >> 4) & 1) * 8) * 272
                            + ((lane >> 3) & 1) * 16);
    const u32 boffB = boffA + 16 * 272;

    const int j = cta * 8 + wid;
    float bg0[4], bg1[4], bif0[4], bif1[4];
#pragma unroll
    for (int g = 0; g < 4; ++g) {
        bg0[g] = d_bias0[g * Hh + j];
        bg1[g] = d_bias1[g * Hh + j];
    }
#pragma unroll
    for (int p = 0; p < 4; ++p) {
        bif0[p] = d_bi0[(lane + 32 * p) * Hh + j];
        bif1[p] = d_bi1[(lane + 32 * p) * Hh + j];
    }
    float c0[4] = {0.f, 0.f, 0.f, 0.f};
    float c1[4] = {0.f, 0.f, 0.f, 0.f};

    for (int t = 0; t < Tt && !g_abort; ++t) {
        const int wr = (t & 1) ^ 1;
#pragma unroll 1
        for (int layer = 0; layer < 2; ++layer) {
            const int nc = layer ? 16 : 9;

            float acc[4][4];
#pragma unroll
            for (int nt = 0; nt < 4; ++nt)
#pragma unroll
                for (int q = 0; q < 4; ++q) acc[nt][q] = 0.f;

            // prologue: 2 chunks in flight
            load_chunk(smA, layer, 0, t, cta, tid);
            CP_COMMIT();
            load_chunk(smA + STG_B, layer, 1, t, cta, tid);
            CP_COMMIT();

#pragma unroll 1
            for (int ci = 0; ci < nc; ++ci) {
                if (ci + 1 < nc) CP_WAIT1(); else CP_WAIT0();
                __syncthreads();

                const u32 SaB  = smA + (u32)(ci % NSTG) * STG_B;
                const u32 actB = SaB;
                const u32 whB  = SaB + 34816;
                const u32 wlB  = SaB + 43520;

                // fragment double-buffered inner loop over 8 k16 steps
                u32 wh[2][4], wl[2][4], b1[2][4], b2[2][4];
                ldsm4(wh[0], whB  + aoffW);
                ldsm4(wl[0], wlB  + aoffW);
                ldsm4(b1[0], actB + boffA);
                ldsm4(b2[0], actB + boffB);
                int cur = 0;
#pragma unroll
                for (int kk = 0; kk < 8; ++kk) {
                    const int nxt = cur ^ 1;
                    if (kk < 7) {
                        const u32 kb = (u32)(kk + 1) * 32;
                        ldsm4(wh[nxt], whB  + aoffW + kb);
                        ldsm4(wl[nxt], wlB  + aoffW + kb);
                        ldsm4(b1[nxt], actB + boffA + kb);
                        ldsm4(b2[nxt], actB + boffB + kb);
                    }
                    mma_f16(acc[0], wh[cur], b1[cur][0], b1[cur][1]);
                    mma_f16(acc[1], wh[cur], b1[cur][2], b1[cur][3]);
                    mma_f16(acc[2], wh[cur], b2[cur][0], b2[cur][1]);
                    mma_f16(acc[3], wh[cur], b2[cur][2], b2[cur][3]);
                    mma_f16(acc[0], wl[cur], b1[cur][0], b1[cur][1]);
                    mma_f16(acc[1], wl[cur], b1[cur][2], b1[cur][3]);
                    mma_f16(acc[2], wl[cur], b2[cur][0], b2[cur][1]);
                    mma_f16(acc[3], wl[cur], b2[cur][2], b2[cur][3]);
                    cur = nxt;
                }

                if (ci + 2 < nc) {
                    load_chunk(smA + (u32)((ci + 2) % NSTG) * STG_B,
                               layer, ci + 2, t, cta, tid);
                    CP_COMMIT();
                }
            }

            // ---- epilogue: acc -> sgate ----
            {
                const int row = mrow * 16 + (lane >> 2);
                const int col = wcol * 32 + (lane & 3) * 2;
#pragma unroll
                for (int nt = 0; nt < 4; ++nt) {
                    const int cb = col + nt * 8;
                    sgate[row * 132 + cb]           = acc[nt][0];
                    sgate[row * 132 + cb + 1]       = acc[nt][1];
                    sgate[(row + 8) * 132 + cb]     = acc[nt][2];
                    sgate[(row + 8) * 132 + cb + 1] = acc[nt][3];
                }
            }
            __syncthreads();

            // ---- cell: unit wid, batches lane+32p ----
            {
                const float* bg  = layer ? bg1 : bg0;
                const float* bif = layer ? bif1 : bif0;
                float* cc = layer ? c1 : c0;
#pragma unroll
                for (int p = 0; p < 4; ++p) {
                    const int b = lane + 32 * p;
                    float pi = sgate[(0  + wid) * 132 + b] + bg[0];
                    float pf = sgate[(8  + wid) * 132 + b] + bg[1] + bif[p];
                    float po = sgate[(16 + wid) * 132 + b] + bg[2];
                    float pg = sgate[(24 + wid) * 132 + b] + bg[3];
                    float iv = sigf(pi), fv = sigf(pf), ov = sigf(po), gg = tanh_f(pg);
                    float cn = fv * cc[p] + iv * gg;
                    cc[p] = cn;
                    float hv = ov * tanh_f(cn);
                    hstg[b * 8 + wid] = __half_as_ushort(__float2half_rn(hv));
                    if (layer == 1 && t == Tt - 1)
                        d_h1f[b * Hh + j] = hv;
                }
            }
            __syncthreads();

            // ---- coalesced h writeback: 16B per batch row ----
            if (tid < 128) {
                const int b = tid;
                uint4 v = *(const uint4*)(hstg + b * 8);
                us* dst = (layer ? &d_h1[wr][b][cta * 8]
                                 : &d_h0[wr][b][cta * 8]);
                *(uint4*)dst = v;
            }

            if (layer == 0) {
                grid_barrier(t + 1);     // single barrier per step
                if (g_abort) break;
            } else {
                __syncthreads();         // protect hstg reuse within CTA
            }
        }
    }
}

// ---------------- fc head ----------------
__global__ void fc_kernel(const float* __restrict__ fcW,
                          const float* __restrict__ fcb,
                          float* __restrict__ out)
{
    __shared__ float red[256];
    int b = blockIdx.x, tid = threadIdx.x;
    float s = 0.f;
    for (int jj = tid; jj < Hh; jj += 256) s += d_h1f[b * Hh + jj] * fcW[jj];
    red[tid] = s;
    __syncthreads();
    for (int o = 128; o > 0; o >>= 1) {
        if (tid < o) red[tid] += red[tid + o];
        __syncthreads();
    }
    if (tid == 0) out[b] = red[0] + fcb[0];
}

// ---------------- launch (5 graph nodes) ----------------
extern "C" void kernel_launch(void* const* d_in, const int* in_sizes, int n_in,
                              void* d_out, int out_size)
{
    const float* x        = (const float*)d_in[0];
    const float* boundary = (const float*)d_in[1];
    const float* Wx0      = (const float*)d_in[2];
    const float* bx0      = (const float*)d_in[3];
    const float* Uh0      = (const float*)d_in[4];
    const float* bh0      = (const float*)d_in[5];
    const float* Wb0      = (const float*)d_in[6];
    const float* bb0      = (const float*)d_in[7];
    const float* Wx1      = (const float*)d_in[8];
    const float* bx1      = (const float*)d_in[9];
    const float* Uh1      = (const float*)d_in[10];
    const float* bh1      = (const float*)d_in[11];
    const float* Wb1      = (const float*)d_in[12];
    const float* bb1      = (const float*)d_in[13];
    const float* fcW      = (const float*)d_in[14];
    const float* fcb      = (const float*)d_in[15];
    float* out            = (float*)d_out;

    cudaFuncSetAttribute(lstm_mma, cudaFuncAttributeMaxDynamicSharedMemorySize, DYN_SMEM);

    setup_misc<<<(Bb * Hh) / 256, 256>>>(boundary, bx0, bh0, bb0, Wb0, bx1, bh1, bb1, Wb1);
    setup_x<<<(Tt * Bb * INP) / 256, 256>>>(x);
    repack_w<<<(128 * 25 * 32 * 128) / 256, 256>>>(Uh0, Wx0, Wx1, Uh1);
    lstm_mma<<<NBLK, NTHR, DYN_SMEM>>>();
    fc_kernel<<<Bb, 256>>>(fcW, fcb, out);
}

// round 15
// speedup vs baseline: 3.6457x; 1.2478x over previous
#include <cuda_runtime.h>
#include <cuda_fp16.h>
#include <math.h>
#include <stdint.h>

// CustomLSTM: 2-layer LSTM, B=128, T=512, IN=64, H=1024, OUT=1
// Round 14: fp16 HMMA, single-plane activations AND single-plane weights
// (weight-quant = zero-mean noise, same class as h-quant; x kept exact via
// the hi|lo column duplication trick). K=128 chunks, 4-stage cp.async,
// fragment double-buffering. 3 ldsm + 4 MMA per k16.

#define Bb    128
#define Tt    512
#define INP   64
#define Hh    1024
#define NBLK  128
#define NTHR  256

typedef unsigned int u32;
typedef unsigned short us;
typedef unsigned long long u64;

// ---- smem layout (bytes) ----
// stage: Act[128 rows][272B] @0 (34816), W[32][272B] @34816 (8704)
#define STG_B    43520u
#define NSTG     4
#define SGATE_B  (NSTG * STG_B)            // 174080: float gate buffer [32][132]
#define HSTG_B   (SGATE_B + 16896u)        // 190976: h staging fp16 [128][8]
#define DYN_SMEM (HSTG_B + 2048u + 256u)   // 193280 bytes

// ---------------- device scratch ----------------
__device__ __align__(128) us d_h0[2][Bb][Hh];      // fp16 bits, single plane
__device__ __align__(128) us d_h1[2][Bb][Hh];
__device__ __align__(128) us d_x[Tt][2][Bb][INP];  // fp16 hi/lo planes
__device__ __align__(128) us d_w[128u * 25u * 32u * 128u];  // [cta][chunk][32][128]
__device__ float d_bias0[4096], d_bias1[4096];
__device__ float d_bi0[Bb * Hh], d_bi1[Bb * Hh];
__device__ float d_h1f[Bb * Hh];
__device__ u32 g_count;
__device__ volatile u32 g_gen;
__device__ volatile u32 g_abort;

// ---------------- helpers ----------------
__device__ __forceinline__ u32 smem_u32(const void* p) {
    u32 a; asm("{ .reg .u64 t; cvta.to.shared.u64 t, %1; cvt.u32.u64 %0, t; }" : "=r"(a) : "l"(p));
    return a;
}
__device__ __forceinline__ void cpa16(u32 dst, const void* src) {
    asm volatile("cp.async.cg.shared.global [%0], [%1], 16;" :: "r"(dst), "l"(src));
}
#define CP_COMMIT() asm volatile("cp.async.commit_group;" ::: "memory")
#define CP_WAIT0()  asm volatile("cp.async.wait_group 0;" ::: "memory")
#define CP_WAIT1()  asm volatile("cp.async.wait_group 1;" ::: "memory")
#define CP_WAIT2()  asm volatile("cp.async.wait_group 2;" ::: "memory")

__device__ __forceinline__ void ldsm4(u32* r, u32 addr) {
    asm volatile("ldmatrix.sync.aligned.m8n8.x4.shared.b16 {%0,%1,%2,%3}, [%4];"
                 : "=r"(r[0]), "=r"(r[1]), "=r"(r[2]), "=r"(r[3]) : "r"(addr));
}
__device__ __forceinline__ void mma_f16(float* c, const u32* a, u32 b0, u32 b1) {
    asm volatile("mma.sync.aligned.m16n8k16.row.col.f32.f16.f16.f32 "
                 "{%0,%1,%2,%3}, {%4,%5,%6,%7}, {%8,%9}, {%0,%1,%2,%3};"
                 : "+f"(c[0]), "+f"(c[1]), "+f"(c[2]), "+f"(c[3])
                 : "r"(a[0]), "r"(a[1]), "r"(a[2]), "r"(a[3]), "r"(b0), "r"(b1));
}

__device__ __forceinline__ float sigf(float x) { return __fdividef(1.f, 1.f + __expf(-x)); }
__device__ __forceinline__ float tanh_f(float x) {
    float xc = fminf(fmaxf(x, -15.f), 15.f);
    float e  = __expf(-2.f * xc);
    return (1.f - e) * __fdividef(1.f, 1.f + e);
}
__device__ __forceinline__ void hsplit(float v, us& hi, us& lo) {
    __half h = __float2half_rn(v);
    __half l = __float2half_rn(v - __half2float(h));
    hi = __half_as_ushort(h); lo = __half_as_ushort(l);
}

// ---------------- setup kernels ----------------
__global__ void setup_misc(const float* __restrict__ boundary,
                           const float* __restrict__ bx0, const float* __restrict__ bh0,
                           const float* __restrict__ bb0, const float* __restrict__ Wb0,
                           const float* __restrict__ bx1, const float* __restrict__ bh1,
                           const float* __restrict__ bb1, const float* __restrict__ Wb1)
{
    int idx = blockIdx.x * 256 + threadIdx.x;   // 131072
    if (idx == 0) { g_count = 0; g_gen = 0; g_abort = 0; }
    ((u32*)d_h0)[idx] = 0u;
    ((u32*)d_h1)[idx] = 0u;
    int b = idx >> 10, j = idx & 1023;
    float p0 = boundary[b * 2 + 0], p1 = boundary[b * 2 + 1];
    d_bi0[idx] = p0 * Wb0[j * 2 + 0] + p1 * Wb0[j * 2 + 1] + bb0[j];
    d_bi1[idx] = p0 * Wb1[j * 2 + 0] + p1 * Wb1[j * 2 + 1] + bb1[j];
    if (idx < 4096) {
        d_bias0[idx] = bx0[idx] + bh0[idx];
        d_bias1[idx] = bx1[idx] + bh1[idx];
    }
}

__global__ void setup_x(const float* __restrict__ x)
{
    int idx = blockIdx.x * 256 + threadIdx.x;   // 4194304
    int k = idx & 63, b = (idx >> 6) & 127, t = idx >> 13;
    float v = x[b * (Tt * INP) + t * INP + k];
    us hi, lo; hsplit(v, hi, lo);
    d_x[t][0][b][k] = hi;
    d_x[t][1][b][k] = lo;
}

// chunk wc: 0-7 Uh0 (K128) | 8 x-special (Wx0_hi duplicated) |
//           9-16 Wx1 (K128) | 17-24 Uh1 (K128)     — single fp16 plane
__global__ void repack_w(const float* __restrict__ Uh0, const float* __restrict__ Wx0,
                         const float* __restrict__ Wx1, const float* __restrict__ Uh1)
{
    int idx = blockIdx.x * 256 + threadIdx.x;   // 128*25*32*128 = 13107200
    int k   = idx & 127;
    int r   = (idx >> 7) & 31;
    int wc  = (idx >> 12) % 25;
    int cta = idx / (25 << 12);
    int grow = (r >> 3) * Hh + cta * 8 + (r & 7);
    float wv;
    if (wc == 8)      wv = Wx0[grow * INP + (k & 63)];   // duplicated across halves
    else if (wc < 8)  wv = Uh0[grow * Hh + wc * 128 + k];
    else if (wc < 17) wv = Wx1[grow * Hh + (wc - 9) * 128 + k];
    else              wv = Uh1[grow * Hh + (wc - 17) * 128 + k];
    d_w[((u64)(cta * 25 + wc)) * 4096u + r * 128 + k] =
        __half_as_ushort(__float2half_rn(wv));
}

// ---------------- grid barrier (bounded, abort-safe) ----------------
__device__ __forceinline__ void grid_barrier(u32 target)
{
    __threadfence();
    __syncthreads();
    if (threadIdx.x == 0) {
        u32 old = atomicAdd(&g_count, 1u);
        if (old == NBLK - 1) {
            g_count = 0;
            __threadfence();
            g_gen = target;
        } else {
            u32 i = 0;
            while (g_gen < target) {
                __nanosleep(64);
                if (g_abort) break;
                if (++i > (1u << 24)) { g_abort = 1u; break; }
            }
        }
    }
    __syncthreads();
}

// ---------------- chunk staging ----------------
// layer0: ci 0..7 h0_prev slices, ci 8 = x special (x_hi | x_lo columns)
// layer1: ci 0..7 h0_new slices, ci 8..15 h1_prev slices
__device__ __forceinline__ void load_chunk(u32 Sa, int layer, int ci, int t, int cta, int tid)
{
    const int rd = t & 1, wr = rd ^ 1;
    const int wc = layer ? (9 + ci) : ci;

    if (layer == 0 && ci == 8) {
        const us* xb = &d_x[t][0][0][0];        // plane stride 8192 us
#pragma unroll
        for (int i = 0; i < 8; ++i) {           // act: 2048 x 16B
            int idx = tid + i * 256;
            int row = idx >> 4, seg = idx & 15;
            const us* src = (seg < 8) ? (xb + row * INP + seg * 8)
                                      : (xb + 8192 + row * INP + (seg - 8) * 8);
            cpa16(Sa + (u32)(row * 272 + seg * 16), src);
        }
    } else {
        const us* aH; int k0;
        if (layer == 0)   { aH = &d_h0[rd][0][0]; k0 = ci * 128; }
        else if (ci < 8)  { aH = &d_h0[wr][0][0]; k0 = ci * 128; }
        else              { aH = &d_h1[rd][0][0]; k0 = (ci - 8) * 128; }
#pragma unroll
        for (int i = 0; i < 8; ++i) {           // act: 2048 x 16B
            int idx = tid + i * 256;
            int row = idx >> 4, seg = idx & 15;
            cpa16(Sa + (u32)(row * 272 + seg * 16), aH + row * Hh + k0 + seg * 8);
        }
    }
    const us* wsrc = d_w + ((u64)(cta * 25 + wc)) * 4096u;
#pragma unroll
    for (int i = 0; i < 2; ++i) {               // W: 512 x 16B
        int idx = tid + i * 256;
        int row = idx >> 4, seg = idx & 15;
        cpa16(Sa + (u32)(34816 + row * 272 + seg * 16),
              wsrc + row * 128 + seg * 8);
    }
}

// ---------------- persistent LSTM kernel ----------------
__global__ void __launch_bounds__(NTHR, 1) lstm_mma()
{
    extern __shared__ __align__(16) uint8_t sm[];
    const int tid  = threadIdx.x;
    const int cta  = blockIdx.x;
    const int lane = tid & 31;
    const int wid  = tid >> 5;
    const int mrow = wid & 1;
    const int wcol = wid >> 1;
    const u32 smA  = smem_u32(sm);

    float* sgate = (float*)(sm + SGATE_B);
    us*    hstg  = (us*)(sm + HSTG_B);          // [128][8] fp16

    // ldmatrix per-lane source byte offsets within a stage (272B rows)
    const u32 aoffW = (u32)((mrow * 16 + (lane & 15)) * 272 + (lane >> 4) * 16);
    const u32 boffA = (u32)((wcol * 32 + (lane & 7) + ((lane >> 4) & 1) * 8) * 272
                            + ((lane >> 3) & 1) * 16);
    const u32 boffB = boffA + 16 * 272;

    const int j = cta * 8 + wid;
    float bg0[4], bg1[4], bif0[4], bif1[4];
#pragma unroll
    for (int g = 0; g < 4; ++g) {
        bg0[g] = d_bias0[g * Hh + j];
        bg1[g] = d_bias1[g * Hh + j];
    }
#pragma unroll
    for (int p = 0; p < 4; ++p) {
        bif0[p] = d_bi0[(lane + 32 * p) * Hh + j];
        bif1[p] = d_bi1[(lane + 32 * p) * Hh + j];
    }
    float c0[4] = {0.f, 0.f, 0.f, 0.f};
    float c1[4] = {0.f, 0.f, 0.f, 0.f};

    for (int t = 0; t < Tt && !g_abort; ++t) {
        const int wr = (t & 1) ^ 1;
#pragma unroll 1
        for (int layer = 0; layer < 2; ++layer) {
            const int nc = layer ? 16 : 9;

            float acc[4][4];
#pragma unroll
            for (int nt = 0; nt < 4; ++nt)
#pragma unroll
                for (int q = 0; q < 4; ++q) acc[nt][q] = 0.f;

            // prologue: 3 chunks in flight
            load_chunk(smA, layer, 0, t, cta, tid);
            CP_COMMIT();
            load_chunk(smA + STG_B, layer, 1, t, cta, tid);
            CP_COMMIT();
            load_chunk(smA + 2 * STG_B, layer, 2, t, cta, tid);
            CP_COMMIT();

#pragma unroll 1
            for (int ci = 0; ci < nc; ++ci) {
                if (ci + 2 < nc)      CP_WAIT2();
                else if (ci + 1 < nc) CP_WAIT1();
                else                  CP_WAIT0();
                __syncthreads();

                const u32 SaB  = smA + (u32)(ci % NSTG) * STG_B;
                const u32 actB = SaB;
                const u32 whB  = SaB + 34816;

                // fragment double-buffered inner loop over 8 k16 steps
                u32 wh[2][4], b1[2][4], b2[2][4];
                ldsm4(wh[0], whB  + aoffW);
                ldsm4(b1[0], actB + boffA);
                ldsm4(b2[0], actB + boffB);
                int cur = 0;
#pragma unroll
                for (int kk = 0; kk < 8; ++kk) {
                    const int nxt = cur ^ 1;
                    if (kk < 7) {
                        const u32 kb = (u32)(kk + 1) * 32;
                        ldsm4(wh[nxt], whB  + aoffW + kb);
                        ldsm4(b1[nxt], actB + boffA + kb);
                        ldsm4(b2[nxt], actB + boffB + kb);
                    }
                    mma_f16(acc[0], wh[cur], b1[cur][0], b1[cur][1]);
                    mma_f16(acc[1], wh[cur], b1[cur][2], b1[cur][3]);
                    mma_f16(acc[2], wh[cur], b2[cur][0], b2[cur][1]);
                    mma_f16(acc[3], wh[cur], b2[cur][2], b2[cur][3]);
                    cur = nxt;
                }

                if (ci + 3 < nc) {
                    load_chunk(smA + (u32)((ci + 3) % NSTG) * STG_B,
                               layer, ci + 3, t, cta, tid);
                    CP_COMMIT();
                }
            }

            // ---- epilogue: acc -> sgate ----
            {
                const int row = mrow * 16 + (lane >> 2);
                const int col = wcol * 32 + (lane & 3) * 2;
#pragma unroll
                for (int nt = 0; nt < 4; ++nt) {
                    const int cb = col + nt * 8;
                    sgate[row * 132 + cb]           = acc[nt][0];
                    sgate[row * 132 + cb + 1]       = acc[nt][1];
                    sgate[(row + 8) * 132 + cb]     = acc[nt][2];
                    sgate[(row + 8) * 132 + cb + 1] = acc[nt][3];
                }
            }
            __syncthreads();

            // ---- cell: unit wid, batches lane+32p ----
            {
                const float* bg  = layer ? bg1 : bg0;
                const float* bif = layer ? bif1 : bif0;
                float* cc = layer ? c1 : c0;
#pragma unroll
                for (int p = 0; p < 4; ++p) {
                    const int b = lane + 32 * p;
                    float pi = sgate[(0  + wid) * 132 + b] + bg[0];
                    float pf = sgate[(8  + wid) * 132 + b] + bg[1] + bif[p];
                    float po = sgate[(16 + wid) * 132 + b] + bg[2];
                    float pg = sgate[(24 + wid) * 132 + b] + bg[3];
                    float iv = sigf(pi), fv = sigf(pf), ov = sigf(po), gg = tanh_f(pg);
                    float cn = fv * cc[p] + iv * gg;
                    cc[p] = cn;
                    float hv = ov * tanh_f(cn);
                    hstg[b * 8 + wid] = __half_as_ushort(__float2half_rn(hv));
                    if (layer == 1 && t == Tt - 1)
                        d_h1f[b * Hh + j] = hv;
                }
            }
            __syncthreads();

            // ---- coalesced h writeback: 16B per batch row ----
            if (tid < 128) {
                const int b = tid;
                uint4 v = *(const uint4*)(hstg + b * 8);
                us* dst = (layer ? &d_h1[wr][b][cta * 8]
                                 : &d_h0[wr][b][cta * 8]);
                *(uint4*)dst = v;
            }

            if (layer == 0) {
                grid_barrier(t + 1);     // single barrier per step
                if (g_abort) break;
            } else {
                __syncthreads();         // protect hstg reuse within CTA
            }
        }
    }
}

// ---------------- fc head ----------------
__global__ void fc_kernel(const float* __restrict__ fcW,
                          const float* __restrict__ fcb,
                          float* __restrict__ out)
{
    __shared__ float red[256];
    int b = blockIdx.x, tid = threadIdx.x;
    float s = 0.f;
    for (int jj = tid; jj < Hh; jj += 256) s += d_h1f[b * Hh + jj] * fcW[jj];
    red[tid] = s;
    __syncthreads();
    for (int o = 128; o > 0; o >>= 1) {
        if (tid < o) red[tid] += red[tid + o];
        __syncthreads();
    }
    if (tid == 0) out[b] = red[0] + fcb[0];
}

// ---------------- launch (5 graph nodes) ----------------
extern "C" void kernel_launch(void* const* d_in, const int* in_sizes, int n_in,
                              void* d_out, int out_size)
{
    const float* x        = (const float*)d_in[0];
    const float* boundary = (const float*)d_in[1];
    const float* Wx0      = (const float*)d_in[2];
    const float* bx0      = (const float*)d_in[3];
    const float* Uh0      = (const float*)d_in[4];
    const float* bh0      = (const float*)d_in[5];
    const float* Wb0      = (const float*)d_in[6];
    const float* bb0      = (const float*)d_in[7];
    const float* Wx1      = (const float*)d_in[8];
    const float* bx1      = (const float*)d_in[9];
    const float* Uh1      = (const float*)d_in[10];
    const float* bh1      = (const float*)d_in[11];
    const float* Wb1      = (const float*)d_in[12];
    const float* bb1      = (const float*)d_in[13];
    const float* fcW      = (const float*)d_in[14];
    const float* fcb      = (const float*)d_in[15];
    float* out            = (float*)d_out;

    cudaFuncSetAttribute(lstm_mma, cudaFuncAttributeMaxDynamicSharedMemorySize, DYN_SMEM);

    setup_misc<<<(Bb * Hh) / 256, 256>>>(boundary, bx0, bh0, bb0, Wb0, bx1, bh1, bb1, Wb1);
    setup_x<<<(Tt * Bb * INP) / 256, 256>>>(x);
    repack_w<<<(128 * 25 * 32 * 128) / 256, 256>>>(Uh0, Wx0, Wx1, Uh1);
    lstm_mma<<<NBLK, NTHR, DYN_SMEM>>>();
    fc_kernel<<<Bb, 256>>>(fcW, fcb, out);
}